// round 1
// baseline (speedup 1.0000x reference)
#include <cuda_runtime.h>
#include <math.h>

#define Bn 32
#define Ln 1024
#define Dn 1024
#define NHn 16
#define HDn 64
#define NCn 64
#define CSn 16
#define In 4096
#define Mn (Bn*Ln)   // 32768 rows

// ---------------- scratch (device globals; no allocation allowed) ----------
__device__ float g_h [(size_t)Mn*Dn];   // ln1 out, later post-norm out
__device__ float g_q [(size_t)Mn*Dn];   // XQ [b][h][l][hd], later y
__device__ float g_k [(size_t)Mn*Dn];   // XK [b][h][l][hd], later h2
__device__ float g_v [(size_t)Mn*Dn];   // XV [b][h][l][hd]
__device__ float g_to[(size_t)Mn*Dn];   // ttt inner output (B,L,D)
__device__ float g_mlp[(size_t)Mn*In];  // gelu(h2@w_in+b_in)
__device__ float g_lr [Bn*NHn*Ln];      // ttt_lr (already sigmoid*BASE_LR/HD)

// ---------------- LayerNorm: one warp per row of 1024 ----------------------
__global__ void ln_kernel(const float* __restrict__ x, const float* __restrict__ w,
                          const float* __restrict__ bb, float* __restrict__ o, float eps) {
    int row  = (blockIdx.x << 3) + (threadIdx.x >> 5);
    int lane = threadIdx.x & 31;
    const float4* xr = (const float4*)(x + (size_t)row * Dn);
    float4 v[8];
    float s = 0.f, s2 = 0.f;
#pragma unroll
    for (int r = 0; r < 8; r++) {
        v[r] = xr[lane + (r << 5)];
        s  += v[r].x + v[r].y + v[r].z + v[r].w;
        s2 += v[r].x*v[r].x + v[r].y*v[r].y + v[r].z*v[r].z + v[r].w*v[r].w;
    }
#pragma unroll
    for (int off = 16; off; off >>= 1) {
        s  += __shfl_xor_sync(0xffffffffu, s,  off);
        s2 += __shfl_xor_sync(0xffffffffu, s2, off);
    }
    float mu  = s * (1.f / 1024.f);
    float var = s2 * (1.f / 1024.f) - mu * mu;
    float rs  = rsqrtf(var + eps);
    const float4* wr = (const float4*)w;
    const float4* br = (const float4*)bb;
    float4* orow = (float4*)(o + (size_t)row * Dn);
#pragma unroll
    for (int r = 0; r < 8; r++) {
        int c = lane + (r << 5);
        float4 W = wr[c], Bv = br[c], X = v[r], O;
        O.x = (X.x - mu) * rs * W.x + Bv.x;
        O.y = (X.y - mu) * rs * W.y + Bv.y;
        O.z = (X.z - mu) * rs * W.z + Bv.z;
        O.w = (X.w - mu) * rs * W.w + Bv.w;
        orow[c] = O;
    }
}

// ---------------- ttt_lr = sigmoid(h . lr_w[h] + lr_b[h]) / HD -------------
__global__ void lr_kernel(const float* __restrict__ lrw, const float* __restrict__ lrb) {
    __shared__ float hs[1024];
    int m = blockIdx.x, t = threadIdx.x;
    ((float4*)hs)[t] = ((const float4*)(g_h + (size_t)m * Dn))[t];
    __syncthreads();
    int w = t >> 5, lane = t & 31;
    for (int hh = w; hh < NHn; hh += 8) {
        const float* lw = lrw + hh * Dn;
        float s = 0.f;
#pragma unroll
        for (int r = 0; r < 32; r++) s += hs[lane + (r << 5)] * lw[lane + (r << 5)];
#pragma unroll
        for (int off = 16; off; off >>= 1) s += __shfl_xor_sync(0xffffffffu, s, off);
        if (lane == 0) {
            float val = (1.f / (1.f + expf(-(s + lrb[hh])))) * (1.f / 64.f);
            int b = m >> 10, l = m & 1023;
            g_lr[(((b << 4) + hh) << 10) + l] = val;
        }
    }
}

// ---------------- SGEMM 128x128 tile, 256 threads, 8x8 per thread ----------
// FLAGS: 1=BIAS, 2=GELU(exact), 4=RESIDUAL add, 8=HEADED output layout
template<int FLAGS>
__global__ void __launch_bounds__(256, 2) sgemm_k(
    const float* __restrict__ A, const float* __restrict__ Bm,
    const float* __restrict__ bias, const float* __restrict__ res,
    float* __restrict__ C, int M, int N, int K)
{
    __shared__ float As[16][128];
    __shared__ float Bs[16][128];
    const int m0 = blockIdx.y << 7, n0 = blockIdx.x << 7;
    const int t = threadIdx.x;
    const int tx = t & 15, ty = t >> 4;
    float acc[8][8];
#pragma unroll
    for (int i = 0; i < 8; i++)
#pragma unroll
        for (int j = 0; j < 8; j++) acc[i][j] = 0.f;

    for (int k0 = 0; k0 < K; k0 += 16) {
#pragma unroll
        for (int u = 0; u < 2; u++) {
            int idx  = t + (u << 8);
            int arow = idx >> 2, ak = (idx & 3) << 2;
            float4 a = *(const float4*)(A + (size_t)(m0 + arow) * K + k0 + ak);
            As[ak + 0][arow] = a.x; As[ak + 1][arow] = a.y;
            As[ak + 2][arow] = a.z; As[ak + 3][arow] = a.w;
            int brow = idx >> 5, bc = (idx & 31) << 2;
            *(float4*)(&Bs[brow][bc]) = *(const float4*)(Bm + (size_t)(k0 + brow) * N + n0 + bc);
        }
        __syncthreads();
#pragma unroll
        for (int k = 0; k < 16; k++) {
            float ar[8], br[8];
            *(float4*)(ar)     = *(const float4*)(&As[k][(ty << 3)]);
            *(float4*)(ar + 4) = *(const float4*)(&As[k][(ty << 3) + 4]);
            *(float4*)(br)     = *(const float4*)(&Bs[k][(tx << 3)]);
            *(float4*)(br + 4) = *(const float4*)(&Bs[k][(tx << 3) + 4]);
#pragma unroll
            for (int i = 0; i < 8; i++)
#pragma unroll
                for (int j = 0; j < 8; j++) acc[i][j] += ar[i] * br[j];
        }
        __syncthreads();
    }

#pragma unroll
    for (int i = 0; i < 8; i++) {
        int row = m0 + (ty << 3) + i;
#pragma unroll
        for (int j = 0; j < 8; j++) {
            int col = n0 + (tx << 3) + j;
            float c = acc[i][j];
            if (FLAGS & 1) c += bias[col];
            if (FLAGS & 2) c = 0.5f * c * (1.f + erff(c * 0.70710678118654752f));
            if (FLAGS & 4) c += res[(size_t)row * N + col];
            if (FLAGS & 8) {
                int b = row >> 10, l = row & 1023, hh = col >> 6, hd = col & 63;
                C[(((size_t)((b << 4) + hh) << 10) + (size_t)l) * 64 + hd] = c;
            } else {
                C[(size_t)row * N + col] = c;
            }
        }
    }
}

// ---------------- TTT inner scan: one block per (b,h), W1/b1 in smem -------
__global__ void __launch_bounds__(256) ttt_scan_kernel(
    const float* __restrict__ W1i, const float* __restrict__ b1i,
    const float* __restrict__ nw,  const float* __restrict__ nb,
    const float* __restrict__ tokp)
{
    __shared__ float W1[4096];               // [k][d] row-major
    __shared__ float b1[64], gam[64], bet[64];
    __shared__ float tki[16], lrs[16];
    __shared__ float xq[1024], xk[1024], xv[1024];
    __shared__ float Zb[1024];               // Z1, then Z1_bar
    __shared__ float G[1024];                // grad
    __shared__ float At[256];                // tril attn

    const int bx = blockIdx.x;
    const int b = bx >> 4, h = bx & 15;
    const int t = threadIdx.x;

    {
        const float* w0 = W1i + h * 4096;
        for (int r = t; r < 4096; r += 256) W1[r] = w0[r];
        if (t < 64) {
            b1[t]  = b1i[(h << 6) + t];
            gam[t] = nw [(h << 6) + t];
            bet[t] = nb [(h << 6) + t];
        }
        if (t < 16) tki[t] = fmaxf(1.f / (float)(t + 1) + tokp[t], 0.f);
    }
    const float4* qb = (const float4*)(g_q + (size_t)bx * Ln * HDn);
    const float4* kb = (const float4*)(g_k + (size_t)bx * Ln * HDn);
    const float4* vb = (const float4*)(g_v + (size_t)bx * Ln * HDn);
    const float*  lrg = g_lr + (size_t)bx * Ln;
    __syncthreads();

    const int d = t & 63, g = t >> 6;      // output col, row-group
    const int wp = t >> 5, lane = t & 31;  // warp mapping for row ops
    const int i0 = g << 2;

    for (int nc = 0; nc < NCn; nc++) {
        ((float4*)xq)[t] = qb[nc * 256 + t];
        ((float4*)xk)[t] = kb[nc * 256 + t];
        ((float4*)xv)[t] = vb[nc * 256 + t];
        if (t < 16) lrs[t] = lrg[(nc << 4) + t];
        __syncthreads();

        // ---- Z1 = xk @ W1 + b1
        {
            float a0 = b1[d], a1 = a0, a2 = a0, a3 = a0;
#pragma unroll
            for (int k4 = 0; k4 < 64; k4 += 4) {
                float4 x0 = *(const float4*)&xk[(i0 + 0) * 64 + k4];
                float4 x1 = *(const float4*)&xk[(i0 + 1) * 64 + k4];
                float4 x2 = *(const float4*)&xk[(i0 + 2) * 64 + k4];
                float4 x3 = *(const float4*)&xk[(i0 + 3) * 64 + k4];
                float w0 = W1[(k4 + 0) * 64 + d], w1 = W1[(k4 + 1) * 64 + d];
                float w2 = W1[(k4 + 2) * 64 + d], w3 = W1[(k4 + 3) * 64 + d];
                a0 += x0.x * w0 + x0.y * w1 + x0.z * w2 + x0.w * w3;
                a1 += x1.x * w0 + x1.y * w1 + x1.z * w2 + x1.w * w3;
                a2 += x2.x * w0 + x2.y * w1 + x2.z * w2 + x2.w * w3;
                a3 += x3.x * w0 + x3.y * w1 + x3.z * w2 + x3.w * w3;
            }
            Zb[(i0 + 0) * 64 + d] = a0; Zb[(i0 + 1) * 64 + d] = a1;
            Zb[(i0 + 2) * 64 + d] = a2; Zb[(i0 + 3) * 64 + d] = a3;
        }
        __syncthreads();

        // ---- grad = ln_fused_l2_bwd(Z1, xv-xk, gamma, beta), eps=1e-6
        {
#pragma unroll
            for (int rr = 0; rr < 2; rr++) {
                int i = (wp << 1) + rr;
                float z0 = Zb[i * 64 + lane], z1 = Zb[i * 64 + lane + 32];
                float s = z0 + z1, s2 = z0 * z0 + z1 * z1;
#pragma unroll
                for (int off = 16; off; off >>= 1) {
                    s  += __shfl_xor_sync(0xffffffffu, s,  off);
                    s2 += __shfl_xor_sync(0xffffffffu, s2, off);
                }
                float mu = s * (1.f / 64.f);
                float var = s2 * (1.f / 64.f) - mu * mu;
                float std = sqrtf(var + 1e-6f);
                float rstd = 1.f / std;
                float xh0 = (z0 - mu) * rstd, xh1 = (z1 - mu) * rstd;
                float g0 = gam[lane], g1 = gam[lane + 32];
                float gx0 = (g0 * xh0 + bet[lane]      - (xv[i * 64 + lane]      - xk[i * 64 + lane]))      * g0;
                float gx1 = (g1 * xh1 + bet[lane + 32] - (xv[i * 64 + lane + 32] - xk[i * 64 + lane + 32])) * g1;
                float sg = gx0 + gx1, sx = gx0 * xh0 + gx1 * xh1;
#pragma unroll
                for (int off = 16; off; off >>= 1) {
                    sg += __shfl_xor_sync(0xffffffffu, sg, off);
                    sx += __shfl_xor_sync(0xffffffffu, sx, off);
                }
                float cc = 1.f / (64.f * std);
                G[i * 64 + lane]      = (64.f * gx0 - sg - xh0 * sx) * cc;
                G[i * 64 + lane + 32] = (64.f * gx1 - sg - xh1 * sx) * cc;
            }
        }
        __syncthreads();

        // ---- Attn = tril(xq @ xk^T)
        {
            int i = t >> 4, j = t & 15;
            float s = 0.f;
            if (j <= i) {
#pragma unroll
                for (int k = 0; k < 64; k += 4) {
                    float4 a = *(const float4*)&xq[i * 64 + k];
                    float4 c = *(const float4*)&xk[j * 64 + k];
                    s += a.x * c.x + a.y * c.y + a.z * c.z + a.w * c.w;
                }
            }
            At[t] = s;
        }
        __syncthreads();

        // ---- Z1_bar = xq@W1 + b1 - sum_{j<=i} tki[i]*lrs[j]*(1+At[i][j])*G[j]
        {
            float ti0 = tki[i0], ti1 = tki[i0 + 1], ti2 = tki[i0 + 2], ti3 = tki[i0 + 3];
            float a0 = b1[d], a1 = a0, a2 = a0, a3 = a0;
#pragma unroll
            for (int j = 0; j < 16; j++) {
                float bbx = lrs[j] * G[j * 64 + d];
                if (j <= i0)     a0 -= ti0 * bbx * (1.f + At[(i0 + 0) * 16 + j]);
                if (j <= i0 + 1) a1 -= ti1 * bbx * (1.f + At[(i0 + 1) * 16 + j]);
                if (j <= i0 + 2) a2 -= ti2 * bbx * (1.f + At[(i0 + 2) * 16 + j]);
                if (j <= i0 + 3) a3 -= ti3 * bbx * (1.f + At[(i0 + 3) * 16 + j]);
            }
#pragma unroll
            for (int k4 = 0; k4 < 64; k4 += 4) {
                float4 x0 = *(const float4*)&xq[(i0 + 0) * 64 + k4];
                float4 x1 = *(const float4*)&xq[(i0 + 1) * 64 + k4];
                float4 x2 = *(const float4*)&xq[(i0 + 2) * 64 + k4];
                float4 x3 = *(const float4*)&xq[(i0 + 3) * 64 + k4];
                float w0 = W1[(k4 + 0) * 64 + d], w1 = W1[(k4 + 1) * 64 + d];
                float w2 = W1[(k4 + 2) * 64 + d], w3 = W1[(k4 + 3) * 64 + d];
                a0 += x0.x * w0 + x0.y * w1 + x0.z * w2 + x0.w * w3;
                a1 += x1.x * w0 + x1.y * w1 + x1.z * w2 + x1.w * w3;
                a2 += x2.x * w0 + x2.y * w1 + x2.z * w2 + x2.w * w3;
                a3 += x3.x * w0 + x3.y * w1 + x3.z * w2 + x3.w * w3;
            }
            Zb[(i0 + 0) * 64 + d] = a0; Zb[(i0 + 1) * 64 + d] = a1;
            Zb[(i0 + 2) * 64 + d] = a2; Zb[(i0 + 3) * 64 + d] = a3;
        }
        __syncthreads();

        // ---- W1 -= xk^T diag(last_eta) grad ; b1 -= last_eta . grad
        {
            float te = tki[15];
            float ge[16];
#pragma unroll
            for (int k = 0; k < 16; k++) ge[k] = lrs[k] * G[k * 64 + d];  // d == e here
            float acc[16];
#pragma unroll
            for (int s_ = 0; s_ < 16; s_++) acc[s_] = 0.f;
#pragma unroll
            for (int k = 0; k < 16; k++) {
                const float4* xr = (const float4*)&xk[k * 64 + (g << 4)];
                float4 x0 = xr[0], x1 = xr[1], x2 = xr[2], x3 = xr[3];
                float gg = ge[k];
                acc[0]  += x0.x * gg; acc[1]  += x0.y * gg; acc[2]  += x0.z * gg; acc[3]  += x0.w * gg;
                acc[4]  += x1.x * gg; acc[5]  += x1.y * gg; acc[6]  += x1.z * gg; acc[7]  += x1.w * gg;
                acc[8]  += x2.x * gg; acc[9]  += x2.y * gg; acc[10] += x2.z * gg; acc[11] += x2.w * gg;
                acc[12] += x3.x * gg; acc[13] += x3.y * gg; acc[14] += x3.z * gg; acc[15] += x3.w * gg;
            }
#pragma unroll
            for (int s_ = 0; s_ < 16; s_++) {
                int dd = (g << 4) + s_;
                W1[dd * 64 + d] -= te * acc[s_];
            }
            if (g == 0) {
                float sb = 0.f;
#pragma unroll
                for (int k = 0; k < 16; k++) sb += ge[k];
                b1[d] -= te * sb;
            }
        }
        __syncthreads();

        // ---- out = xq + LN(Z1_bar, gamma, beta, eps=1e-6) -> g_to (B,L,D)
        {
#pragma unroll
            for (int rr = 0; rr < 2; rr++) {
                int i = (wp << 1) + rr;
                float z0 = Zb[i * 64 + lane], z1 = Zb[i * 64 + lane + 32];
                float s = z0 + z1, s2 = z0 * z0 + z1 * z1;
#pragma unroll
                for (int off = 16; off; off >>= 1) {
                    s  += __shfl_xor_sync(0xffffffffu, s,  off);
                    s2 += __shfl_xor_sync(0xffffffffu, s2, off);
                }
                float mu = s * (1.f / 64.f);
                float var = s2 * (1.f / 64.f) - mu * mu;
                float rs = rsqrtf(var + 1e-6f);
                float o0 = xq[i * 64 + lane]      + (z0 - mu) * rs * gam[lane]      + bet[lane];
                float o1 = xq[i * 64 + lane + 32] + (z1 - mu) * rs * gam[lane + 32] + bet[lane + 32];
                size_t row = (size_t)(b << 10) + (nc << 4) + i;
                g_to[row * 1024 + (h << 6) + lane]      = o0;
                g_to[row * 1024 + (h << 6) + lane + 32] = o1;
            }
        }
        __syncthreads();
    }
}

// ---------------- launch ----------------------------------------------------
extern "C" void kernel_launch(void* const* d_in, const int* in_sizes, int n_in,
                              void* d_out, int out_size) {
    (void)in_sizes; (void)n_in; (void)out_size;
    const float* x    = (const float*)d_in[0];
    // d_in[1] = position_ids (int64, unused)
    const float* ln1w = (const float*)d_in[2];
    const float* ln1b = (const float*)d_in[3];
    const float* wq   = (const float*)d_in[4];
    const float* wk   = (const float*)d_in[5];
    const float* wv   = (const float*)d_in[6];
    const float* wo   = (const float*)d_in[7];
    const float* W1i  = (const float*)d_in[8];
    const float* b1i  = (const float*)d_in[9];
    const float* nw   = (const float*)d_in[10];
    const float* nb   = (const float*)d_in[11];
    const float* lrw  = (const float*)d_in[12];
    const float* lrb  = (const float*)d_in[13];
    const float* tokp = (const float*)d_in[14];
    const float* pnw  = (const float*)d_in[15];
    const float* pnb  = (const float*)d_in[16];
    const float* ln2w = (const float*)d_in[17];
    const float* ln2b = (const float*)d_in[18];
    const float* win  = (const float*)d_in[19];
    const float* bin  = (const float*)d_in[20];
    const float* wout = (const float*)d_in[21];
    const float* bout = (const float*)d_in[22];
    float* out = (float*)d_out;

    float *ph, *pq, *pk, *pv, *pt, *pm;
    cudaGetSymbolAddress((void**)&ph, g_h);
    cudaGetSymbolAddress((void**)&pq, g_q);
    cudaGetSymbolAddress((void**)&pk, g_k);
    cudaGetSymbolAddress((void**)&pv, g_v);
    cudaGetSymbolAddress((void**)&pt, g_to);
    cudaGetSymbolAddress((void**)&pm, g_mlp);

    dim3 g1(Dn / 128, Mn / 128);   // (8, 256)
    dim3 g2(In / 128, Mn / 128);   // (32, 256)

    // h = LN(x)
    ln_kernel<<<Mn / 8, 256>>>(x, ln1w, ln1b, ph, 1e-5f);
    // ttt_lr
    lr_kernel<<<Mn, 256>>>(lrw, lrb);
    // XQ/XK/XV in [b][h][l][hd] layout
    sgemm_k<8><<<g1, 256>>>(ph, wq, nullptr, nullptr, pq, Mn, Dn, Dn);
    sgemm_k<8><<<g1, 256>>>(ph, wk, nullptr, nullptr, pk, Mn, Dn, Dn);
    sgemm_k<8><<<g1, 256>>>(ph, wv, nullptr, nullptr, pv, Mn, Dn, Dn);
    // sequential TTT scan -> g_to (B,L,D)
    ttt_scan_kernel<<<Bn * NHn, 256>>>(W1i, b1i, nw, nb, tokp);
    // post-norm
    ln_kernel<<<Mn / 8, 256>>>(pt, pnw, pnb, ph, 1e-5f);
    // y = x + pn @ wo   (into g_q)
    sgemm_k<4><<<g1, 256>>>(ph, wo, nullptr, x, pq, Mn, Dn, Dn);
    // h2 = LN(y)
    ln_kernel<<<Mn / 8, 256>>>(pq, ln2w, ln2b, pk, 1e-5f);
    // mlp hidden = gelu(h2 @ w_in + b_in)
    sgemm_k<3><<<g2, 256>>>(pk, win, bin, nullptr, pm, Mn, In, Dn);
    // out = y + mlp @ w_out + b_out
    sgemm_k<5><<<g1, 256>>>(pm, wout, bout, pq, out, Mn, Dn, In);
}

// round 2
// speedup vs baseline: 2.4171x; 2.4171x over previous
#include <cuda_runtime.h>
#include <math.h>

#define Bn 32
#define Ln 1024
#define Dn 1024
#define NHn 16
#define HDn 64
#define NCn 64
#define CSn 16
#define In 4096
#define Mn (Bn*Ln)   // 32768 rows

// ---------------- scratch (device globals; no allocation allowed) ----------
__device__ float g_h [(size_t)Mn*Dn];
__device__ float g_q [(size_t)Mn*Dn];
__device__ float g_k [(size_t)Mn*Dn];
__device__ float g_v [(size_t)Mn*Dn];
__device__ float g_to[(size_t)Mn*Dn];
__device__ float g_mlp[(size_t)Mn*In];
__device__ float g_lr [Bn*NHn*Ln];

// ---------------- LayerNorm: one warp per row of 1024 ----------------------
__global__ void ln_kernel(const float* __restrict__ x, const float* __restrict__ w,
                          const float* __restrict__ bb, float* __restrict__ o, float eps) {
    int row  = (blockIdx.x << 3) + (threadIdx.x >> 5);
    int lane = threadIdx.x & 31;
    const float4* xr = (const float4*)(x + (size_t)row * Dn);
    float4 v[8];
    float s = 0.f, s2 = 0.f;
#pragma unroll
    for (int r = 0; r < 8; r++) {
        v[r] = xr[lane + (r << 5)];
        s  += v[r].x + v[r].y + v[r].z + v[r].w;
        s2 += v[r].x*v[r].x + v[r].y*v[r].y + v[r].z*v[r].z + v[r].w*v[r].w;
    }
#pragma unroll
    for (int off = 16; off; off >>= 1) {
        s  += __shfl_xor_sync(0xffffffffu, s,  off);
        s2 += __shfl_xor_sync(0xffffffffu, s2, off);
    }
    float mu  = s * (1.f / 1024.f);
    float var = s2 * (1.f / 1024.f) - mu * mu;
    float rs  = rsqrtf(var + eps);
    const float4* wr = (const float4*)w;
    const float4* br = (const float4*)bb;
    float4* orow = (float4*)(o + (size_t)row * Dn);
#pragma unroll
    for (int r = 0; r < 8; r++) {
        int c = lane + (r << 5);
        float4 W = wr[c], Bv = br[c], X = v[r], O;
        O.x = (X.x - mu) * rs * W.x + Bv.x;
        O.y = (X.y - mu) * rs * W.y + Bv.y;
        O.z = (X.z - mu) * rs * W.z + Bv.z;
        O.w = (X.w - mu) * rs * W.w + Bv.w;
        orow[c] = O;
    }
}

// ---------------- ttt_lr = sigmoid(h . lr_w[h] + lr_b[h]) / HD -------------
__global__ void lr_kernel(const float* __restrict__ lrw, const float* __restrict__ lrb) {
    __shared__ float hs[1024];
    int m = blockIdx.x, t = threadIdx.x;
    ((float4*)hs)[t] = ((const float4*)(g_h + (size_t)m * Dn))[t];
    __syncthreads();
    int w = t >> 5, lane = t & 31;
    for (int hh = w; hh < NHn; hh += 8) {
        const float* lw = lrw + hh * Dn;
        float s = 0.f;
#pragma unroll
        for (int r = 0; r < 32; r++) s += hs[lane + (r << 5)] * lw[lane + (r << 5)];
#pragma unroll
        for (int off = 16; off; off >>= 1) s += __shfl_xor_sync(0xffffffffu, s, off);
        if (lane == 0) {
            float val = (1.f / (1.f + expf(-(s + lrb[hh])))) * (1.f / 64.f);
            int b = m >> 10, l = m & 1023;
            g_lr[(((b << 4) + hh) << 10) + l] = val;
        }
    }
}

// ---------------- tf32 tensor-core GEMM -------------------------------------
#define ASTR 36
#define BSTR 136
#define STAGE_F (128*ASTR + 32*BSTR)
#define GEMM_SMEM (STAGE_F*2*4)

__device__ __forceinline__ float totf(float x) {
    unsigned r;
    asm("cvt.rna.tf32.f32 %0, %1;" : "=r"(r) : "f"(x));
    return __uint_as_float(r);
}
__device__ __forceinline__ void mma8(float* c, const unsigned* a, const unsigned* b) {
    asm volatile(
        "mma.sync.aligned.m16n8k8.row.col.f32.tf32.tf32.f32 "
        "{%0,%1,%2,%3},{%4,%5,%6,%7},{%8,%9},{%0,%1,%2,%3};"
        : "+f"(c[0]), "+f"(c[1]), "+f"(c[2]), "+f"(c[3])
        : "r"(a[0]), "r"(a[1]), "r"(a[2]), "r"(a[3]), "r"(b[0]), "r"(b[1]));
}

// FLAGS: 1=BIAS, 2=GELU(exact), 4=RESIDUAL add, 8=HEADED output layout
template<int FLAGS>
__global__ void __launch_bounds__(256, 2) gemm_tc(
    const float* __restrict__ A, const float* __restrict__ Bm,
    const float* __restrict__ bias, const float* __restrict__ res,
    float* __restrict__ C, int M, int N, int K)
{
    extern __shared__ float sm[];
    const int m0 = blockIdx.y << 7, n0 = blockIdx.x << 7;
    const int t = threadIdx.x;
    const int warp = t >> 5, lane = t & 31;
    const int wm = warp >> 1, wn = warp & 1;
    const int gq = lane >> 2, gr = lane & 3;

    float acc[2][8][4];
#pragma unroll
    for (int mt = 0; mt < 2; mt++)
#pragma unroll
        for (int nt = 0; nt < 8; nt++)
#pragma unroll
            for (int e = 0; e < 4; e++) acc[mt][nt][e] = 0.f;

    const int nslab = K >> 5;
    float4 ra[4], rb[4];

#pragma unroll
    for (int p = 0; p < 4; p++) {
        int ia = (p << 8) + t;
        ra[p] = *(const float4*)(A + (size_t)(m0 + (ia >> 3)) * K + ((ia & 7) << 2));
        rb[p] = *(const float4*)(Bm + (size_t)(ia >> 5) * N + n0 + ((ia & 31) << 2));
    }

    for (int s = 0; s < nslab; s++) {
        float* As = sm + (s & 1) * STAGE_F;
        float* Bs = As + 128 * ASTR;
#pragma unroll
        for (int p = 0; p < 4; p++) {
            int ia = (p << 8) + t;
            float4 va = ra[p];
            float* da = As + (ia >> 3) * ASTR + ((ia & 7) << 2);
            da[0] = totf(va.x); da[1] = totf(va.y); da[2] = totf(va.z); da[3] = totf(va.w);
            float4 vb = rb[p];
            float* db = Bs + (ia >> 5) * BSTR + ((ia & 31) << 2);
            db[0] = totf(vb.x); db[1] = totf(vb.y); db[2] = totf(vb.z); db[3] = totf(vb.w);
        }
        __syncthreads();
        if (s + 1 < nslab) {
            int k0 = (s + 1) << 5;
#pragma unroll
            for (int p = 0; p < 4; p++) {
                int ia = (p << 8) + t;
                ra[p] = *(const float4*)(A + (size_t)(m0 + (ia >> 3)) * K + k0 + ((ia & 7) << 2));
                rb[p] = *(const float4*)(Bm + (size_t)(k0 + (ia >> 5)) * N + n0 + ((ia & 31) << 2));
            }
        }
#pragma unroll
        for (int kk = 0; kk < 4; kk++) {
            unsigned afr[2][4];
            const int col = (kk << 3) + gr;
#pragma unroll
            for (int mt = 0; mt < 2; mt++) {
                int r = (wm << 5) + (mt << 4) + gq;
                afr[mt][0] = __float_as_uint(As[r * ASTR + col]);
                afr[mt][1] = __float_as_uint(As[(r + 8) * ASTR + col]);
                afr[mt][2] = __float_as_uint(As[r * ASTR + col + 4]);
                afr[mt][3] = __float_as_uint(As[(r + 8) * ASTR + col + 4]);
            }
            const int kb = (kk << 3) + gr;
#pragma unroll
            for (int nt = 0; nt < 8; nt++) {
                unsigned bfr[2];
                int n = (wn << 6) + (nt << 3) + gq;
                bfr[0] = __float_as_uint(Bs[kb * BSTR + n]);
                bfr[1] = __float_as_uint(Bs[(kb + 4) * BSTR + n]);
                mma8(acc[0][nt], afr[0], bfr);
                mma8(acc[1][nt], afr[1], bfr);
            }
        }
        __syncthreads();
    }

#pragma unroll
    for (int mt = 0; mt < 2; mt++) {
#pragma unroll
        for (int nt = 0; nt < 8; nt++) {
#pragma unroll
            for (int half = 0; half < 2; half++) {
                int row = m0 + (wm << 5) + (mt << 4) + gq + (half << 3);
                int col = n0 + (wn << 6) + (nt << 3) + (gr << 1);
                float v0 = acc[mt][nt][half * 2 + 0];
                float v1 = acc[mt][nt][half * 2 + 1];
                if (FLAGS & 1) { v0 += bias[col]; v1 += bias[col + 1]; }
                if (FLAGS & 2) {
                    v0 = 0.5f * v0 * (1.f + erff(v0 * 0.70710678118654752f));
                    v1 = 0.5f * v1 * (1.f + erff(v1 * 0.70710678118654752f));
                }
                if (FLAGS & 4) {
                    float2 r2 = *(const float2*)(res + (size_t)row * N + col);
                    v0 += r2.x; v1 += r2.y;
                }
                if (FLAGS & 8) {
                    int b = row >> 10, l = row & 1023, hh = col >> 6, hd = col & 63;
                    float2* dst = (float2*)(C + ((((size_t)((b << 4) + hh) << 10) + l) << 6) + hd);
                    *dst = make_float2(v0, v1);
                } else {
                    *(float2*)(C + (size_t)row * N + col) = make_float2(v0, v1);
                }
            }
        }
    }
}

// ---------------- TTT inner scan: one block per (b,h), W1/b1 in smem -------
__global__ void __launch_bounds__(256) ttt_scan_kernel(
    const float* __restrict__ W1i, const float* __restrict__ b1i,
    const float* __restrict__ nw,  const float* __restrict__ nb,
    const float* __restrict__ tokp)
{
    __shared__ float W1[4096];
    __shared__ float b1[64], gam[64], bet[64];
    __shared__ float tki[16], lrs[16];
    __shared__ float xq[1024], xk[1024], xv[1024];
    __shared__ float Zb[1024];
    __shared__ float G[1024];
    __shared__ float At[256];

    const int bx = blockIdx.x;
    const int b = bx >> 4, h = bx & 15;
    const int t = threadIdx.x;

    {
        const float* w0 = W1i + h * 4096;
        for (int r = t; r < 4096; r += 256) W1[r] = w0[r];
        if (t < 64) {
            b1[t]  = b1i[(h << 6) + t];
            gam[t] = nw [(h << 6) + t];
            bet[t] = nb [(h << 6) + t];
        }
        if (t < 16) tki[t] = fmaxf(1.f / (float)(t + 1) + tokp[t], 0.f);
    }
    const float4* qb = (const float4*)(g_q + (size_t)bx * Ln * HDn);
    const float4* kb = (const float4*)(g_k + (size_t)bx * Ln * HDn);
    const float4* vb = (const float4*)(g_v + (size_t)bx * Ln * HDn);
    const float*  lrg = g_lr + (size_t)bx * Ln;
    __syncthreads();

    const int d = t & 63, g = t >> 6;
    const int wp = t >> 5, lane = t & 31;
    const int i0 = g << 2;

    for (int nc = 0; nc < NCn; nc++) {
        ((float4*)xq)[t] = qb[nc * 256 + t];
        ((float4*)xk)[t] = kb[nc * 256 + t];
        ((float4*)xv)[t] = vb[nc * 256 + t];
        if (t < 16) lrs[t] = lrg[(nc << 4) + t];
        __syncthreads();

        {
            float a0 = b1[d], a1 = a0, a2 = a0, a3 = a0;
#pragma unroll
            for (int k4 = 0; k4 < 64; k4 += 4) {
                float4 x0 = *(const float4*)&xk[(i0 + 0) * 64 + k4];
                float4 x1 = *(const float4*)&xk[(i0 + 1) * 64 + k4];
                float4 x2 = *(const float4*)&xk[(i0 + 2) * 64 + k4];
                float4 x3 = *(const float4*)&xk[(i0 + 3) * 64 + k4];
                float w0 = W1[(k4 + 0) * 64 + d], w1 = W1[(k4 + 1) * 64 + d];
                float w2 = W1[(k4 + 2) * 64 + d], w3 = W1[(k4 + 3) * 64 + d];
                a0 += x0.x * w0 + x0.y * w1 + x0.z * w2 + x0.w * w3;
                a1 += x1.x * w0 + x1.y * w1 + x1.z * w2 + x1.w * w3;
                a2 += x2.x * w0 + x2.y * w1 + x2.z * w2 + x2.w * w3;
                a3 += x3.x * w0 + x3.y * w1 + x3.z * w2 + x3.w * w3;
            }
            Zb[(i0 + 0) * 64 + d] = a0; Zb[(i0 + 1) * 64 + d] = a1;
            Zb[(i0 + 2) * 64 + d] = a2; Zb[(i0 + 3) * 64 + d] = a3;
        }
        __syncthreads();

        {
#pragma unroll
            for (int rr = 0; rr < 2; rr++) {
                int i = (wp << 1) + rr;
                float z0 = Zb[i * 64 + lane], z1 = Zb[i * 64 + lane + 32];
                float s = z0 + z1, s2 = z0 * z0 + z1 * z1;
#pragma unroll
                for (int off = 16; off; off >>= 1) {
                    s  += __shfl_xor_sync(0xffffffffu, s,  off);
                    s2 += __shfl_xor_sync(0xffffffffu, s2, off);
                }
                float mu = s * (1.f / 64.f);
                float var = s2 * (1.f / 64.f) - mu * mu;
                float std = sqrtf(var + 1e-6f);
                float rstd = 1.f / std;
                float xh0 = (z0 - mu) * rstd, xh1 = (z1 - mu) * rstd;
                float g0 = gam[lane], g1 = gam[lane + 32];
                float gx0 = (g0 * xh0 + bet[lane]      - (xv[i * 64 + lane]      - xk[i * 64 + lane]))      * g0;
                float gx1 = (g1 * xh1 + bet[lane + 32] - (xv[i * 64 + lane + 32] - xk[i * 64 + lane + 32])) * g1;
                float sg = gx0 + gx1, sx = gx0 * xh0 + gx1 * xh1;
#pragma unroll
                for (int off = 16; off; off >>= 1) {
                    sg += __shfl_xor_sync(0xffffffffu, sg, off);
                    sx += __shfl_xor_sync(0xffffffffu, sx, off);
                }
                float cc = 1.f / (64.f * std);
                G[i * 64 + lane]      = (64.f * gx0 - sg - xh0 * sx) * cc;
                G[i * 64 + lane + 32] = (64.f * gx1 - sg - xh1 * sx) * cc;
            }
        }
        __syncthreads();

        {
            int i = t >> 4, j = t & 15;
            float s = 0.f;
            if (j <= i) {
#pragma unroll
                for (int k = 0; k < 64; k += 4) {
                    float4 a = *(const float4*)&xq[i * 64 + k];
                    float4 c = *(const float4*)&xk[j * 64 + k];
                    s += a.x * c.x + a.y * c.y + a.z * c.z + a.w * c.w;
                }
            }
            At[t] = s;
        }
        __syncthreads();

        {
            float ti0 = tki[i0], ti1 = tki[i0 + 1], ti2 = tki[i0 + 2], ti3 = tki[i0 + 3];
            float a0 = b1[d], a1 = a0, a2 = a0, a3 = a0;
#pragma unroll
            for (int j = 0; j < 16; j++) {
                float bbx = lrs[j] * G[j * 64 + d];
                if (j <= i0)     a0 -= ti0 * bbx * (1.f + At[(i0 + 0) * 16 + j]);
                if (j <= i0 + 1) a1 -= ti1 * bbx * (1.f + At[(i0 + 1) * 16 + j]);
                if (j <= i0 + 2) a2 -= ti2 * bbx * (1.f + At[(i0 + 2) * 16 + j]);
                if (j <= i0 + 3) a3 -= ti3 * bbx * (1.f + At[(i0 + 3) * 16 + j]);
            }
#pragma unroll
            for (int k4 = 0; k4 < 64; k4 += 4) {
                float4 x0 = *(const float4*)&xq[(i0 + 0) * 64 + k4];
                float4 x1 = *(const float4*)&xq[(i0 + 1) * 64 + k4];
                float4 x2 = *(const float4*)&xq[(i0 + 2) * 64 + k4];
                float4 x3 = *(const float4*)&xq[(i0 + 3) * 64 + k4];
                float w0 = W1[(k4 + 0) * 64 + d], w1 = W1[(k4 + 1) * 64 + d];
                float w2 = W1[(k4 + 2) * 64 + d], w3 = W1[(k4 + 3) * 64 + d];
                a0 += x0.x * w0 + x0.y * w1 + x0.z * w2 + x0.w * w3;
                a1 += x1.x * w0 + x1.y * w1 + x1.z * w2 + x1.w * w3;
                a2 += x2.x * w0 + x2.y * w1 + x2.z * w2 + x2.w * w3;
                a3 += x3.x * w0 + x3.y * w1 + x3.z * w2 + x3.w * w3;
            }
            Zb[(i0 + 0) * 64 + d] = a0; Zb[(i0 + 1) * 64 + d] = a1;
            Zb[(i0 + 2) * 64 + d] = a2; Zb[(i0 + 3) * 64 + d] = a3;
        }
        __syncthreads();

        {
            float te = tki[15];
            float ge[16];
#pragma unroll
            for (int k = 0; k < 16; k++) ge[k] = lrs[k] * G[k * 64 + d];
            float acc[16];
#pragma unroll
            for (int s_ = 0; s_ < 16; s_++) acc[s_] = 0.f;
#pragma unroll
            for (int k = 0; k < 16; k++) {
                const float4* xr = (const float4*)&xk[k * 64 + (g << 4)];
                float4 x0 = xr[0], x1 = xr[1], x2 = xr[2], x3 = xr[3];
                float gg = ge[k];
                acc[0]  += x0.x * gg; acc[1]  += x0.y * gg; acc[2]  += x0.z * gg; acc[3]  += x0.w * gg;
                acc[4]  += x1.x * gg; acc[5]  += x1.y * gg; acc[6]  += x1.z * gg; acc[7]  += x1.w * gg;
                acc[8]  += x2.x * gg; acc[9]  += x2.y * gg; acc[10] += x2.z * gg; acc[11] += x2.w * gg;
                acc[12] += x3.x * gg; acc[13] += x3.y * gg; acc[14] += x3.z * gg; acc[15] += x3.w * gg;
            }
#pragma unroll
            for (int s_ = 0; s_ < 16; s_++) {
                int dd = (g << 4) + s_;
                W1[dd * 64 + d] -= te * acc[s_];
            }
            if (g == 0) {
                float sb = 0.f;
#pragma unroll
                for (int k = 0; k < 16; k++) sb += ge[k];
                b1[d] -= te * sb;
            }
        }
        __syncthreads();

        {
#pragma unroll
            for (int rr = 0; rr < 2; rr++) {
                int i = (wp << 1) + rr;
                float z0 = Zb[i * 64 + lane], z1 = Zb[i * 64 + lane + 32];
                float s = z0 + z1, s2 = z0 * z0 + z1 * z1;
#pragma unroll
                for (int off = 16; off; off >>= 1) {
                    s  += __shfl_xor_sync(0xffffffffu, s,  off);
                    s2 += __shfl_xor_sync(0xffffffffu, s2, off);
                }
                float mu = s * (1.f / 64.f);
                float var = s2 * (1.f / 64.f) - mu * mu;
                float rs = rsqrtf(var + 1e-6f);
                float o0 = xq[i * 64 + lane]      + (z0 - mu) * rs * gam[lane]      + bet[lane];
                float o1 = xq[i * 64 + lane + 32] + (z1 - mu) * rs * gam[lane + 32] + bet[lane + 32];
                size_t row = (size_t)(b << 10) + (nc << 4) + i;
                g_to[row * 1024 + (h << 6) + lane]      = o0;
                g_to[row * 1024 + (h << 6) + lane + 32] = o1;
            }
        }
        __syncthreads();
    }
}

// ---------------- launch ----------------------------------------------------
extern "C" void kernel_launch(void* const* d_in, const int* in_sizes, int n_in,
                              void* d_out, int out_size) {
    (void)in_sizes; (void)n_in; (void)out_size;
    const float* x    = (const float*)d_in[0];
    const float* ln1w = (const float*)d_in[2];
    const float* ln1b = (const float*)d_in[3];
    const float* wq   = (const float*)d_in[4];
    const float* wk   = (const float*)d_in[5];
    const float* wv   = (const float*)d_in[6];
    const float* wo   = (const float*)d_in[7];
    const float* W1i  = (const float*)d_in[8];
    const float* b1i  = (const float*)d_in[9];
    const float* nw   = (const float*)d_in[10];
    const float* nb   = (const float*)d_in[11];
    const float* lrw  = (const float*)d_in[12];
    const float* lrb  = (const float*)d_in[13];
    const float* tokp = (const float*)d_in[14];
    const float* pnw  = (const float*)d_in[15];
    const float* pnb  = (const float*)d_in[16];
    const float* ln2w = (const float*)d_in[17];
    const float* ln2b = (const float*)d_in[18];
    const float* win  = (const float*)d_in[19];
    const float* bin  = (const float*)d_in[20];
    const float* wout = (const float*)d_in[21];
    const float* bout = (const float*)d_in[22];
    float* out = (float*)d_out;

    float *ph, *pq, *pk, *pv, *pt, *pm;
    cudaGetSymbolAddress((void**)&ph, g_h);
    cudaGetSymbolAddress((void**)&pq, g_q);
    cudaGetSymbolAddress((void**)&pk, g_k);
    cudaGetSymbolAddress((void**)&pv, g_v);
    cudaGetSymbolAddress((void**)&pt, g_to);
    cudaGetSymbolAddress((void**)&pm, g_mlp);

    cudaFuncSetAttribute(gemm_tc<8>, cudaFuncAttributeMaxDynamicSharedMemorySize, GEMM_SMEM);
    cudaFuncSetAttribute(gemm_tc<4>, cudaFuncAttributeMaxDynamicSharedMemorySize, GEMM_SMEM);
    cudaFuncSetAttribute(gemm_tc<3>, cudaFuncAttributeMaxDynamicSharedMemorySize, GEMM_SMEM);
    cudaFuncSetAttribute(gemm_tc<5>, cudaFuncAttributeMaxDynamicSharedMemorySize, GEMM_SMEM);

    dim3 g1(Dn / 128, Mn / 128);   // (8, 256)
    dim3 g2(In / 128, Mn / 128);   // (32, 256)

    ln_kernel<<<Mn / 8, 256>>>(x, ln1w, ln1b, ph, 1e-5f);
    lr_kernel<<<Mn, 256>>>(lrw, lrb);
    gemm_tc<8><<<g1, 256, GEMM_SMEM>>>(ph, wq, nullptr, nullptr, pq, Mn, Dn, Dn);
    gemm_tc<8><<<g1, 256, GEMM_SMEM>>>(ph, wk, nullptr, nullptr, pk, Mn, Dn, Dn);
    gemm_tc<8><<<g1, 256, GEMM_SMEM>>>(ph, wv, nullptr, nullptr, pv, Mn, Dn, Dn);
    ttt_scan_kernel<<<Bn * NHn, 256>>>(W1i, b1i, nw, nb, tokp);
    ln_kernel<<<Mn / 8, 256>>>(pt, pnw, pnb, ph, 1e-5f);
    gemm_tc<4><<<g1, 256, GEMM_SMEM>>>(ph, wo, nullptr, x, pq, Mn, Dn, Dn);
    ln_kernel<<<Mn / 8, 256>>>(pq, ln2w, ln2b, pk, 1e-5f);
    gemm_tc<3><<<g2, 256, GEMM_SMEM>>>(pk, win, bin, nullptr, pm, Mn, In, Dn);
    gemm_tc<5><<<g1, 256, GEMM_SMEM>>>(pm, wout, bout, pq, out, Mn, Dn, In);
}